// round 14
// baseline (speedup 1.0000x reference)
#include <cuda_runtime.h>
#include <cuda_fp16.h>
#include <cstdint>

#define NT 2560
#define DD 32
#define NB 4
#define BN 32
#define BM 128
#define MSPLIT 4
#define NITH 5                        // m-tiles per unit (20 / MSPLIT)
#define NTHREADS 256
#define NUNITS (80 * NB * MSPLIT)     // 1280 work units
#define NPERS 444                     // persistent CTAs = 148 SMs x occ 3

// ---- layer-kernel smem ----
#define SM_XNH 0
#define SM_BUF 2560
#define OFF_XMH 0
#define OFF_HTH 10240
#define BUFSZ   18944                 // per stage (XM + HT)
#define SMEM_P  (SM_BUF + 3 * BUFSZ)  // 59392, 3-stage ring
#define SM_AGG  SM_BUF                // 16KB reduction buffer (post-loop)
#define SM_W    (SM_AGG + 16384)      // 8320B weights (epilogue only)
#define SM_OUT  (SM_W + 8320)         // 32x33 f32 out tile (epilogue only)

// ---- device globals (allocation-free scratch) ----
__device__ float    g_h1 [NB * NT * DD];
__device__ float    g_agg[MSPLIT * NB * NT * DD];
__device__ uint32_t g_xhi  [NB * NT * DD / 2];  // X fp16x2 [b][row][16]
__device__ uint32_t g_hthi [NB * DD * NT / 2];  // H^T fp16x2, layer-0 input (X^T)
__device__ uint32_t g_hthi2[NB * DD * NT / 2];  // H^T fp16x2, layer-1 input (h1^T)
__device__ int      g_cnt[80 * NB];             // last-unit counters (self-reset)

__device__ __forceinline__ uint32_t smem_u32(const void* p) {
  uint32_t a;
  asm("{ .reg .u64 t; cvta.to.shared.u64 t, %1; cvt.u32.u64 %0, t; }" : "=r"(a) : "l"(p));
  return a;
}
__device__ __forceinline__ void mma16816(float c[4], const uint32_t a[4],
                                         const uint32_t b[2]) {
  asm volatile(
      "mma.sync.aligned.m16n8k16.row.col.f32.f16.f16.f32 "
      "{%0,%1,%2,%3}, {%4,%5,%6,%7}, {%8,%9}, {%0,%1,%2,%3};"
      : "+f"(c[0]), "+f"(c[1]), "+f"(c[2]), "+f"(c[3])
      : "r"(a[0]), "r"(a[1]), "r"(a[2]), "r"(a[3]), "r"(b[0]), "r"(b[1]));
}
__device__ __forceinline__ void ldsm4(uint32_t r[4], uint32_t addr) {
  asm volatile("ldmatrix.sync.aligned.m8n8.x4.shared.b16 {%0,%1,%2,%3}, [%4];"
               : "=r"(r[0]), "=r"(r[1]), "=r"(r[2]), "=r"(r[3]) : "r"(addr));
}
__device__ __forceinline__ void cp16(uint32_t dst, const void* src) {
  asm volatile("cp.async.ca.shared.global [%0], [%1], 16;" :: "r"(dst), "l"(src));
}
#define CP_COMMIT() asm volatile("cp.async.commit_group;")
template <int N> __device__ __forceinline__ void cp_wait() {
  asm volatile("cp.async.wait_group %0;" :: "n"(N));
}
__device__ __forceinline__ float tanh_relu(float s) {
  float r = fmaxf(s, 0.0f), v;
  asm("tanh.approx.f32 %0, %1;" : "=f"(v) : "f"(r));
  return v;
}
__device__ __forceinline__ uint32_t pack_h2(float x, float y) {
  __half2 h = __floats2half2_rn(x, y);
  return *reinterpret_cast<uint32_t*>(&h);
}

// ---- prep: fp16-convert X rows + write transposed fp16 (once) ----
__global__ void prep_kernel(const float* __restrict__ src) {
  __shared__ uint32_t sxh[16][20];
  const int t = threadIdx.x, b = blockIdx.y, r0 = blockIdx.x * 16;
  {
    const int row = t >> 3, q = t & 7;
    float4 v = *(const float4*)(src + ((size_t)b * NT + r0 + row) * DD + q * 4);
    uint32_t h0 = pack_h2(v.x, v.y), h1 = pack_h2(v.z, v.w);
    sxh[row][q * 2] = h0; sxh[row][q * 2 + 1] = h1;
    *(uint2*)&g_xhi[((size_t)b * NT + r0 + row) * 16 + q * 2] = make_uint2(h0, h1);
  }
  __syncthreads();
  {
    #pragma unroll
    for (int k = 0; k < 2; ++k) {
      const int i = t + k * 128;
      const int d = i >> 3, p = i & 7;
      const uint32_t sh = (d & 1) * 16;
      uint32_t h0 = (sxh[2 * p][d >> 1] >> sh) & 0xffffu;
      uint32_t h1 = (sxh[2 * p + 1][d >> 1] >> sh) & 0xffffu;
      g_hthi[((size_t)b * DD + d) * (NT / 2) + (r0 >> 1) + p] = h0 | (h1 << 16);
    }
  }
}

// ---- persistent fused layer: 444 CTAs, static unit schedule ----
__global__ __launch_bounds__(NTHREADS, 3)
void gnn_layer(const float* __restrict__ hin_p,
               const float* __restrict__ Ws, const float* __restrict__ Wn,
               const float* __restrict__ bias, float* __restrict__ hout_p,
               int layer)
{
  extern __shared__ char sm[];
  const uint32_t sb = smem_u32(sm);
  const int t = threadIdx.x, lane = t & 31, wid = t >> 5;
  const int wr = wid >> 2, wc = wid & 3, g = lane >> 2, tig = lane & 3;

  const uint32_t* __restrict__ hth = layer ? g_hthi2 : g_hthi;

  // ---- ldmatrix lane addresses (unit-invariant) ----
  const uint32_t a_addr = sb + SM_XNH +
      (uint32_t)(16 * wr + 8 * ((lane >> 3) & 1) + (lane & 7)) * 80u +
      (uint32_t)(lane >> 4) * 16u;
  const uint32_t b1_addr = OFF_XMH +
      (uint32_t)(32 * wc + 8 * (lane >> 4) + (lane & 7)) * 80u +
      (uint32_t)((lane >> 3) & 1) * 16u;
  const uint32_t b2_addr = OFF_HTH +
      (uint32_t)(8 * (lane >> 4) + (lane & 7)) * 272u +
      (uint32_t)(64 * wc) + (uint32_t)((lane >> 3) & 1) * 16u;

  __shared__ int s_last;

  for (int u = blockIdx.x; u < NUNITS; u += NPERS) {
    const int bx = u % 80;
    const int b  = (u / 80) & (NB - 1);
    const int mz = u / (80 * NB);
    const int n0 = bx * BN;
    const int mtdiag = bx >> 2, doff = (bx & 3) * 32;

    // ---- Xn tile for this unit: 32 rows x 64B fp16 ----
    {
      const int row = t >> 3, q = t & 7;
      const size_t xi = ((size_t)b * NT + n0 + row) * 16 + q * 2;
      *(uint2*)(sm + SM_XNH + row * 80 + q * 8) = *(const uint2*)(g_xhi + xi);
    }

    // tile-issue via cp.async (4x16B per thread); 3-stage ring
    auto issue = [&](int i) {
      const int m0 = (mz * NITH + i) * BM;
      const uint32_t base = sb + SM_BUF + (uint32_t)(i % 3) * BUFSZ;
      const size_t xbase = ((size_t)b * NT + m0) * 16;
      const size_t hbase = (size_t)b * DD * (NT / 2) + (m0 >> 1);
      #pragma unroll
      for (int k = 0; k < 2; ++k) {
        const int c = t + k * 256;
        const int row = c >> 2, q = c & 3;
        cp16(base + OFF_XMH + row * 80 + q * 16, g_xhi + xbase + row * 16 + q * 4);
        const int d = c >> 4, q2 = c & 15;
        cp16(base + OFF_HTH + d * 272 + q2 * 16,
             hth + hbase + (size_t)d * (NT / 2) + q2 * 4);
      }
      CP_COMMIT();
    };

    float acc2[4][4];
    #pragma unroll
    for (int nc = 0; nc < 4; ++nc)
      #pragma unroll
      for (int e = 0; e < 4; ++e) acc2[nc][e] = 0.0f;

    issue(0);
    __syncthreads();                     // Xn stores visible

    uint32_t AH[2][4];                   // unit-invariant A (Xn)
    ldsm4(AH[0], a_addr);
    ldsm4(AH[1], a_addr + 32);

    for (int i = 0; i < NITH; ++i) {
      if (i + 1 < NITH) { issue(i + 1); cp_wait<1>(); }
      else              { cp_wait<0>(); }
      __syncthreads();

      const uint32_t buf = sb + SM_BUF + (uint32_t)(i % 3) * BUFSZ;
      const int mt = mz * NITH + i;
      const bool diag = (mt == mtdiag);

      uint32_t BH[2][2][4], BH2[2][2][4];
      #pragma unroll
      for (int kt = 0; kt < 2; ++kt)
        #pragma unroll
        for (int p = 0; p < 2; ++p) {
          ldsm4(BH[kt][p],  buf + b1_addr + p * 1280u + kt * 32u);
          ldsm4(BH2[kt][p], buf + b2_addr + p * 4352u + kt * 32u);
        }

      // ---- phase 1: S = Xn·Xm^T ----
      float acc[4][4];
      #pragma unroll
      for (int mc = 0; mc < 4; ++mc)
        #pragma unroll
        for (int e = 0; e < 4; ++e) acc[mc][e] = 0.0f;
      #pragma unroll
      for (int kt = 0; kt < 2; ++kt)
        #pragma unroll
        for (int mc = 0; mc < 4; ++mc)
          mma16816(acc[mc], AH[kt], &BH[kt][mc >> 1][(mc & 1) * 2]);

      // ---- nonlinearity (f32 tanh.approx) + self-loop -> phase-2 A frags ----
      uint32_t sA2[8];
      #pragma unroll
      for (int mc = 0; mc < 4; ++mc) {
        float v0 = tanh_relu(acc[mc][0]);
        float v1 = tanh_relu(acc[mc][1]);
        float v2 = tanh_relu(acc[mc][2]);
        float v3 = tanh_relu(acc[mc][3]);
        if (diag) {
          const int nl = 16 * wr + g;
          const int ml = 32 * wc + 8 * mc + 2 * tig;
          if (ml     == nl + doff)     v0 += 0.5f;
          if (ml + 1 == nl + doff)     v1 += 0.5f;
          if (ml     == nl + 8 + doff) v2 += 0.5f;
          if (ml + 1 == nl + 8 + doff) v3 += 0.5f;
        }
        sA2[2 * mc]     = pack_h2(v0, v1);
        sA2[2 * mc + 1] = pack_h2(v2, v3);
      }

      // ---- phase 2: agg += S·H ----
      #pragma unroll
      for (int kt = 0; kt < 2; ++kt)
        #pragma unroll
        for (int nc = 0; nc < 4; ++nc)
          mma16816(acc2[nc], &sA2[4 * kt], &BH2[kt][nc >> 1][(nc & 1) * 2]);
    }

    __syncthreads();   // buf region dead -> reduction buffer

    // ---- cross-warp reduction of agg (4 m-slices) ----
    float* aggbuf = (float*)(sm + SM_AGG);
    {
      float* p = aggbuf + wc * 1024;
      const int nl = 16 * wr + g;
      #pragma unroll
      for (int nc = 0; nc < 4; ++nc) {
        const int d0 = 8 * nc + 2 * tig;
        p[nl * 32 + d0]           = acc2[nc][0];
        p[nl * 32 + d0 + 1]       = acc2[nc][1];
        p[(nl + 8) * 32 + d0]     = acc2[nc][2];
        p[(nl + 8) * 32 + d0 + 1] = acc2[nc][3];
      }
    }
    __syncthreads();

    // ---- reduce 4 slices + write partial agg to this unit's slot ----
    {
      float4* a4 = (float4*)aggbuf;
      float4 s = a4[t], s1 = a4[t + 256], s2 = a4[t + 512], s3 = a4[t + 768];
      float4 r = make_float4(s.x + s1.x + s2.x + s3.x, s.y + s1.y + s2.y + s3.y,
                             s.z + s1.z + s2.z + s3.z, s.w + s1.w + s2.w + s3.w);
      float4* gout = (float4*)(g_agg + (((size_t)(mz * NB + b)) * NT + n0) * DD);
      gout[t] = r;
    }

    // ---- last-unit detection for (bx, b) ----
    __threadfence();
    __syncthreads();
    if (t == 0) {
      int old = atomicAdd(&g_cnt[bx * NB + b], 1);
      s_last = (old == MSPLIT - 1);
      if (old == MSPLIT - 1) g_cnt[bx * NB + b] = 0;   // self-reset
    }
    __syncthreads();

    if (s_last) {
      __threadfence();
      // ---- epilogue: out = elu(h·Ws + sum(agg)·Wn + b) ----
      const float* Hin  = hin_p  ? hin_p  : (const float*)g_h1;
      float*       Hout = hout_p ? hout_p : g_h1;

      float* sW = (float*)(sm + SM_W);
      for (int i = t; i < 2 * DD * DD + DD; i += NTHREADS) {
        float v;
        if (i < 1024)      v = Ws[i];
        else if (i < 2048) v = Wn[i - 1024];
        else               v = bias[i - 2048];
        sW[i] = v;
      }
      __syncthreads();

      const int r = t >> 3, e0 = (t & 7) * 4;
      float h[DD], a[DD];
      {
        const float4* hr = (const float4*)(Hin + ((size_t)b * NT + n0 + r) * DD);
        #pragma unroll
        for (int q = 0; q < 8; ++q) {
          float4 v = hr[q];
          h[4 * q] = v.x; h[4 * q + 1] = v.y; h[4 * q + 2] = v.z; h[4 * q + 3] = v.w;
          float4 s = make_float4(0.f, 0.f, 0.f, 0.f);
          #pragma unroll
          for (int z = 0; z < MSPLIT; ++z) {
            float4 x = __ldcg((const float4*)(g_agg +
                         (((size_t)(z * NB + b)) * NT + n0 + r) * DD) + q);
            s.x += x.x; s.y += x.y; s.z += x.z; s.w += x.w;
          }
          a[4 * q] = s.x; a[4 * q + 1] = s.y; a[4 * q + 2] = s.z; a[4 * q + 3] = s.w;
        }
      }
      float out[4];
      #pragma unroll
      for (int e = 0; e < 4; ++e) out[e] = sW[2048 + e0 + e];
      #pragma unroll
      for (int d = 0; d < DD; ++d) {
        const float hd = h[d];
        const float ad = a[d];
        const float* ws = sW + d * DD + e0;
        const float* wn = sW + 1024 + d * DD + e0;
        #pragma unroll
        for (int e = 0; e < 4; ++e) out[e] += hd * ws[e] + ad * wn[e];
      }
      #pragma unroll
      for (int e = 0; e < 4; ++e) {
        float v = out[e];
        out[e] = v > 0.0f ? v : (__expf(v) - 1.0f);
      }
      *(float4*)(Hout + ((size_t)b * NT + n0 + r) * DD + e0) =
          make_float4(out[0], out[1], out[2], out[3]);

      // ---- fused next-layer prep: transposed fp16 write to OTHER buffer ----
      if (layer == 0) {
        float* sOut = (float*)(sm + SM_OUT);           // [32][33]
        #pragma unroll
        for (int e = 0; e < 4; ++e) sOut[r * 33 + e0 + e] = out[e];
        __syncthreads();
        #pragma unroll
        for (int k = 0; k < 2; ++k) {
          const int i = t + k * 256;                   // 512 = 32d x 16p
          const int d = i >> 4, p = i & 15;
          g_hthi2[((size_t)b * DD + d) * (NT / 2) + (n0 >> 1) + p] =
              pack_h2(sOut[(2 * p) * 33 + d], sOut[(2 * p + 1) * 33 + d]);
        }
      }
    }
    __syncthreads();   // smem (stages/sW/sOut/s_last) safe to reuse next unit
  }
}

extern "C" void kernel_launch(void* const* d_in, const int* in_sizes, int n_in,
                              void* d_out, int out_size) {
  (void)in_sizes; (void)n_in; (void)out_size;
  const float* X  = (const float*)d_in[0];
  const float* Ws = (const float*)d_in[1];   // [2,32,32]
  const float* Wn = (const float*)d_in[2];   // [2,32,32]
  const float* bb = (const float*)d_in[3];   // [2,32]
  float* out = (float*)d_out;

  cudaFuncSetAttribute(gnn_layer,
                       cudaFuncAttributeMaxDynamicSharedMemorySize, SMEM_P);

  dim3 pgrid(NT / 16, NB), pblk(128);
  dim3 ggrid(NPERS), gblk(NTHREADS);

  prep_kernel<<<pgrid, pblk>>>(X);                               // g_xhi, g_hthi(X)
  gnn_layer<<<ggrid, gblk, SMEM_P>>>(X, Ws, Wn, bb, nullptr, 0); // -> g_h1 + g_hthi2
  gnn_layer<<<ggrid, gblk, SMEM_P>>>(nullptr, Ws + 1024, Wn + 1024, bb + 32, out, 1);
}

// round 15
// speedup vs baseline: 1.1716x; 1.1716x over previous
#include <cuda_runtime.h>
#include <cuda_fp16.h>
#include <cstdint>

#define NT 2560
#define DD 32
#define NB 4
#define BN 32
#define BM 128
#define MSPLIT 2
#define NITH 10                       // m-tiles per block (20 / MSPLIT)
#define NTHREADS 256

// ---- layer-kernel smem ----
#define SM_XNH 0
#define SM_BUF 2560
#define OFF_XMH 0
#define OFF_HTH 10240
#define BUFSZ   18944                 // per stage (XM + HT)
#define SMEM_P  (SM_BUF + 3 * BUFSZ)  // 59392, 3-stage ring
#define SM_AGG  SM_BUF                // 16KB reduction buffer (post-loop)
#define SM_W    (SM_AGG + 16384)      // 8320B weights (epilogue only)
#define SM_OUT  (SM_W + 8320)         // 32x33 f32 out tile (epilogue only)

// ---- device globals (allocation-free scratch) ----
__device__ float    g_h1 [NB * NT * DD];
__device__ float    g_agg[MSPLIT * NB * NT * DD];
__device__ uint32_t g_xhi  [NB * NT * DD / 2];  // X fp16x2 [b][row][16]
__device__ uint32_t g_hthi [NB * DD * NT / 2];  // H^T fp16x2, layer-0 input (X^T)
__device__ uint32_t g_hthi2[NB * DD * NT / 2];  // H^T fp16x2, layer-1 input (h1^T)
__device__ int      g_cnt[80 * NB];             // last-block counters (self-reset)

__device__ __forceinline__ uint32_t smem_u32(const void* p) {
  uint32_t a;
  asm("{ .reg .u64 t; cvta.to.shared.u64 t, %1; cvt.u32.u64 %0, t; }" : "=r"(a) : "l"(p));
  return a;
}
__device__ __forceinline__ void mma16816(float c[4], const uint32_t a[4],
                                         const uint32_t b[2]) {
  asm volatile(
      "mma.sync.aligned.m16n8k16.row.col.f32.f16.f16.f32 "
      "{%0,%1,%2,%3}, {%4,%5,%6,%7}, {%8,%9}, {%0,%1,%2,%3};"
      : "+f"(c[0]), "+f"(c[1]), "+f"(c[2]), "+f"(c[3])
      : "r"(a[0]), "r"(a[1]), "r"(a[2]), "r"(a[3]), "r"(b[0]), "r"(b[1]));
}
__device__ __forceinline__ void ldsm4(uint32_t r[4], uint32_t addr) {
  asm volatile("ldmatrix.sync.aligned.m8n8.x4.shared.b16 {%0,%1,%2,%3}, [%4];"
               : "=r"(r[0]), "=r"(r[1]), "=r"(r[2]), "=r"(r[3]) : "r"(addr));
}
__device__ __forceinline__ void cp16(uint32_t dst, const void* src) {
  asm volatile("cp.async.cg.shared.global [%0], [%1], 16;" :: "r"(dst), "l"(src));
}
#define CP_COMMIT() asm volatile("cp.async.commit_group;")
template <int N> __device__ __forceinline__ void cp_wait() {
  asm volatile("cp.async.wait_group %0;" :: "n"(N));
}
__device__ __forceinline__ float tanh_relu(float s) {
  float r = fmaxf(s, 0.0f), v;
  asm("tanh.approx.f32 %0, %1;" : "=f"(v) : "f"(r));
  return v;
}
__device__ __forceinline__ uint32_t pack_h2(float x, float y) {
  __half2 h = __floats2half2_rn(x, y);
  return *reinterpret_cast<uint32_t*>(&h);
}
__device__ __forceinline__ int atomic_add_acqrel(int* p, int v) {
  int old;
  asm volatile("atom.add.acq_rel.gpu.global.s32 %0, [%1], %2;"
               : "=r"(old) : "l"(p), "r"(v) : "memory");
  return old;
}

// ---- prep: fp16-convert X rows + write transposed fp16 (once) ----
// grid (NT/16, NB), 128 threads, 16 rows per block
__global__ void prep_kernel(const float* __restrict__ src) {
  __shared__ uint32_t sxh[16][20];
  const int t = threadIdx.x, b = blockIdx.y, r0 = blockIdx.x * 16;
  {
    const int row = t >> 3, q = t & 7;
    float4 v = *(const float4*)(src + ((size_t)b * NT + r0 + row) * DD + q * 4);
    uint32_t h0 = pack_h2(v.x, v.y), h1 = pack_h2(v.z, v.w);
    sxh[row][q * 2] = h0; sxh[row][q * 2 + 1] = h1;
    *(uint2*)&g_xhi[((size_t)b * NT + r0 + row) * 16 + q * 2] = make_uint2(h0, h1);
  }
  __syncthreads();
  {
    #pragma unroll
    for (int k = 0; k < 2; ++k) {
      const int i = t + k * 128;
      const int d = i >> 3, p = i & 7;
      const uint32_t sh = (d & 1) * 16;
      uint32_t h0 = (sxh[2 * p][d >> 1] >> sh) & 0xffffu;
      uint32_t h1 = (sxh[2 * p + 1][d >> 1] >> sh) & 0xffffu;
      g_hthi[((size_t)b * DD + d) * (NT / 2) + (r0 >> 1) + p] = h0 | (h1 << 16);
    }
  }
}

// ---- fused layer: partial agg (10 m-tiles) + last-block epilogue ----
// layer=0: HT read g_hthi, epilogue prep-writes g_hthi2. layer=1: read g_hthi2.
__global__ __launch_bounds__(NTHREADS, 3)
void gnn_layer(const float* __restrict__ hin_p,
               const float* __restrict__ Ws, const float* __restrict__ Wn,
               const float* __restrict__ bias, float* __restrict__ hout_p,
               int layer)
{
  extern __shared__ char sm[];
  const uint32_t sb = smem_u32(sm);
  const int t = threadIdx.x, lane = t & 31, wid = t >> 5;
  const int wr = wid >> 2, wc = wid & 3, g = lane >> 2, tig = lane & 3;
  const int bx = blockIdx.x, b = blockIdx.y, mz = blockIdx.z;
  const int n0 = bx * BN;
  const int mtdiag = bx >> 2, doff = (bx & 3) * 32;

  const uint32_t* __restrict__ hth = layer ? g_hthi2 : g_hthi;  // disjoint from writer

  // Xn tile (persistent): 32 rows x 64B fp16
  {
    const int row = t >> 3, q = t & 7;
    const size_t xi = ((size_t)b * NT + n0 + row) * 16 + q * 2;
    *(uint2*)(sm + SM_XNH + row * 80 + q * 8) = *(const uint2*)(g_xhi + xi);
  }

  // tile-issue via cp.async (4x16B per thread); 3-stage ring
  auto issue = [&](int i) {
    const int m0 = (mz * NITH + i) * BM;
    const uint32_t base = sb + SM_BUF + (uint32_t)(i % 3) * BUFSZ;
    const size_t xbase = ((size_t)b * NT + m0) * 16;
    const size_t hbase = (size_t)b * DD * (NT / 2) + (m0 >> 1);
    #pragma unroll
    for (int k = 0; k < 2; ++k) {
      const int c = t + k * 256;
      const int row = c >> 2, q = c & 3;
      cp16(base + OFF_XMH + row * 80 + q * 16, g_xhi + xbase + row * 16 + q * 4);
      const int d = c >> 4, q2 = c & 15;
      cp16(base + OFF_HTH + d * 272 + q2 * 16,
           hth + hbase + (size_t)d * (NT / 2) + q2 * 4);
    }
    CP_COMMIT();
  };

  // ---- ldmatrix lane addresses ----
  const uint32_t a_addr = sb + SM_XNH +
      (uint32_t)(16 * wr + 8 * ((lane >> 3) & 1) + (lane & 7)) * 80u +
      (uint32_t)(lane >> 4) * 16u;
  const uint32_t b1_addr = OFF_XMH +
      (uint32_t)(32 * wc + 8 * (lane >> 4) + (lane & 7)) * 80u +
      (uint32_t)((lane >> 3) & 1) * 16u;
  const uint32_t b2_addr = OFF_HTH +
      (uint32_t)(8 * (lane >> 4) + (lane & 7)) * 272u +
      (uint32_t)(64 * wc) + (uint32_t)((lane >> 3) & 1) * 16u;

  float acc2[4][4];
  #pragma unroll
  for (int nc = 0; nc < 4; ++nc)
    #pragma unroll
    for (int e = 0; e < 4; ++e) acc2[nc][e] = 0.0f;

  issue(0);
  __syncthreads();                       // Xn stores visible

  uint32_t AH[2][4];                     // loop-invariant A (Xn)
  ldsm4(AH[0], a_addr);
  ldsm4(AH[1], a_addr + 32);

  for (int i = 0; i < NITH; ++i) {
    if (i + 1 < NITH) { issue(i + 1); cp_wait<1>(); }
    else              { cp_wait<0>(); }
    __syncthreads();   // 3-stage ring: refilled stage last read 2 iters ago

    const uint32_t buf = sb + SM_BUF + (uint32_t)(i % 3) * BUFSZ;
    const int mt = mz * NITH + i;
    const bool diag = (mt == mtdiag);

    uint32_t BH[2][2][4], BH2[2][2][4];
    #pragma unroll
    for (int kt = 0; kt < 2; ++kt)
      #pragma unroll
      for (int p = 0; p < 2; ++p) {
        ldsm4(BH[kt][p],  buf + b1_addr + p * 1280u + kt * 32u);
        ldsm4(BH2[kt][p], buf + b2_addr + p * 4352u + kt * 32u);
      }

    // ---- phase 1: S = Xn·Xm^T ----
    float acc[4][4];
    #pragma unroll
    for (int mc = 0; mc < 4; ++mc)
      #pragma unroll
      for (int e = 0; e < 4; ++e) acc[mc][e] = 0.0f;
    #pragma unroll
    for (int kt = 0; kt < 2; ++kt)
      #pragma unroll
      for (int mc = 0; mc < 4; ++mc)
        mma16816(acc[mc], AH[kt], &BH[kt][mc >> 1][(mc & 1) * 2]);

    // ---- nonlinearity (f32 tanh.approx) + self-loop -> phase-2 A frags ----
    uint32_t sA2[8];
    #pragma unroll
    for (int mc = 0; mc < 4; ++mc) {
      float v0 = tanh_relu(acc[mc][0]);
      float v1 = tanh_relu(acc[mc][1]);
      float v2 = tanh_relu(acc[mc][2]);
      float v3 = tanh_relu(acc[mc][3]);
      if (diag) {
        const int nl = 16 * wr + g;
        const int ml = 32 * wc + 8 * mc + 2 * tig;
        if (ml     == nl + doff)     v0 += 0.5f;
        if (ml + 1 == nl + doff)     v1 += 0.5f;
        if (ml     == nl + 8 + doff) v2 += 0.5f;
        if (ml + 1 == nl + 8 + doff) v3 += 0.5f;
      }
      sA2[2 * mc]     = pack_h2(v0, v1);
      sA2[2 * mc + 1] = pack_h2(v2, v3);
    }

    // ---- phase 2: agg += S·H ----
    #pragma unroll
    for (int kt = 0; kt < 2; ++kt)
      #pragma unroll
      for (int nc = 0; nc < 4; ++nc)
        mma16816(acc2[nc], &sA2[4 * kt], &BH2[kt][nc >> 1][(nc & 1) * 2]);
  }

  __syncthreads();   // buf region dead -> reduction buffer

  // ---- cross-warp reduction of agg (4 m-slices) ----
  float* aggbuf = (float*)(sm + SM_AGG);
  {
    float* p = aggbuf + wc * 1024;
    const int nl = 16 * wr + g;
    #pragma unroll
    for (int nc = 0; nc < 4; ++nc) {
      const int d0 = 8 * nc + 2 * tig;
      p[nl * 32 + d0]           = acc2[nc][0];
      p[nl * 32 + d0 + 1]       = acc2[nc][1];
      p[(nl + 8) * 32 + d0]     = acc2[nc][2];
      p[(nl + 8) * 32 + d0 + 1] = acc2[nc][3];
    }
  }
  __syncthreads();

  // ---- reduce 4 slices (kept in smem) + write partial agg to global slot ----
  {
    float4* a4 = (float4*)aggbuf;
    float4 s = a4[t], s1 = a4[t + 256], s2 = a4[t + 512], s3 = a4[t + 768];
    float4 r = make_float4(s.x + s1.x + s2.x + s3.x, s.y + s1.y + s2.y + s3.y,
                           s.z + s1.z + s2.z + s3.z, s.w + s1.w + s2.w + s3.w);
    a4[t] = r;                                    // own reduced partial -> smem
    float4* gout = (float4*)(g_agg + (((size_t)(mz * NB + b)) * NT + n0) * DD);
    gout[t] = r;
  }

  // ---- last-block detection (release-acquire atomic; no explicit fences) ----
  __shared__ int s_last;
  __syncthreads();                                // all STGs issued pre-atomic
  if (t == 0) {
    int old = atomic_add_acqrel(&g_cnt[bx * NB + b], 1);
    s_last = (old == MSPLIT - 1);
    if (old == MSPLIT - 1) g_cnt[bx * NB + b] = 0;   // self-reset for next launch
  }
  __syncthreads();
  if (!s_last) return;

  // ---- epilogue (last block only): out = elu(h·Ws + (own+peer)·Wn + b) ----
  const float* Hin  = hin_p  ? hin_p  : (const float*)g_h1;
  float*       Hout = hout_p ? hout_p : g_h1;

  float* sW = (float*)(sm + SM_W);
  for (int i = t; i < 2 * DD * DD + DD; i += NTHREADS) {
    float v;
    if (i < 1024)      v = Ws[i];
    else if (i < 2048) v = Wn[i - 1024];
    else               v = bias[i - 2048];
    sW[i] = v;
  }
  __syncthreads();

  const int r = t >> 3, e0 = (t & 7) * 4;
  const int pz = mz ^ 1;                          // peer slot
  float h[DD], a[DD];
  {
    const float4* hr = (const float4*)(Hin + ((size_t)b * NT + n0 + r) * DD);
    const float4* pp = (const float4*)(g_agg + (((size_t)(pz * NB + b)) * NT + n0 + r) * DD);
    const float4* own = (const float4*)(aggbuf + r * DD);
    #pragma unroll
    for (int q = 0; q < 8; ++q) {
      float4 v = hr[q];
      h[4 * q] = v.x; h[4 * q + 1] = v.y; h[4 * q + 2] = v.z; h[4 * q + 3] = v.w;
      float4 x0 = own[q];                          // own partial from smem
      float4 x1 = __ldcg(pp + q);                  // peer via L2
      a[4 * q]     = x0.x + x1.x; a[4 * q + 1] = x0.y + x1.y;
      a[4 * q + 2] = x0.z + x1.z; a[4 * q + 3] = x0.w + x1.w;
    }
  }
  float out[4];
  #pragma unroll
  for (int e = 0; e < 4; ++e) out[e] = sW[2048 + e0 + e];
  #pragma unroll
  for (int d = 0; d < DD; ++d) {
    const float hd = h[d];
    const float ad = a[d];
    const float* ws = sW + d * DD + e0;
    const float* wn = sW + 1024 + d * DD + e0;
    #pragma unroll
    for (int e = 0; e < 4; ++e) out[e] += hd * ws[e] + ad * wn[e];
  }
  #pragma unroll
  for (int e = 0; e < 4; ++e) {
    float v = out[e];
    out[e] = v > 0.0f ? v : (__expf(v) - 1.0f);
  }
  *(float4*)(Hout + ((size_t)b * NT + n0 + r) * DD + e0) =
      make_float4(out[0], out[1], out[2], out[3]);

  // ---- fused next-layer prep: transposed fp16 write to the OTHER buffer ----
  if (layer == 0) {
    float* sOut = (float*)(sm + SM_OUT);           // [32][33]
    #pragma unroll
    for (int e = 0; e < 4; ++e) sOut[r * 33 + e0 + e] = out[e];
    __syncthreads();
    #pragma unroll
    for (int k = 0; k < 2; ++k) {
      const int i = t + k * 256;                   // 512 = 32d x 16p
      const int d = i >> 4, p = i & 15;
      g_hthi2[((size_t)b * DD + d) * (NT / 2) + (n0 >> 1) + p] =
          pack_h2(sOut[(2 * p) * 33 + d], sOut[(2 * p + 1) * 33 + d]);
    }
  }
}

extern "C" void kernel_launch(void* const* d_in, const int* in_sizes, int n_in,
                              void* d_out, int out_size) {
  (void)in_sizes; (void)n_in; (void)out_size;
  const float* X  = (const float*)d_in[0];
  const float* Ws = (const float*)d_in[1];   // [2,32,32]
  const float* Wn = (const float*)d_in[2];   // [2,32,32]
  const float* bb = (const float*)d_in[3];   // [2,32]
  float* out = (float*)d_out;

  cudaFuncSetAttribute(gnn_layer,
                       cudaFuncAttributeMaxDynamicSharedMemorySize, SMEM_P);

  dim3 pgrid(NT / 16, NB), pblk(128);
  dim3 ggrid(80, NB, MSPLIT), gblk(NTHREADS);

  prep_kernel<<<pgrid, pblk>>>(X);                               // g_xhi, g_hthi(X)
  gnn_layer<<<ggrid, gblk, SMEM_P>>>(X, Ws, Wn, bb, nullptr, 0); // -> g_h1 + g_hthi2
  gnn_layer<<<ggrid, gblk, SMEM_P>>>(nullptr, Ws + 1024, Wn + 1024, bb + 32, out, 1);
}

// round 16
// speedup vs baseline: 1.2124x; 1.0348x over previous
#include <cuda_runtime.h>
#include <cuda_fp16.h>
#include <cstdint>

#define NT 2560
#define DD 32
#define NB 4
#define BN 32
#define BM 128
#define MSPLIT 2
#define NITH 10                       // m-tiles per block (20 / MSPLIT)
#define NTHREADS 256

// ---- layer-kernel smem ----
#define SM_XNH 0
#define SM_BUF 2560
#define SM_AGG SM_BUF                 // 16KB reduction buffer (post-loop)
#define SM_W   (SM_AGG + 16384)       // 8320B weights (epilogue only)
// L0: stage 10240 (X tile only) x 4 stages -> smem 43520
// L1: stage 20480 (X tile @0, H tile @10240) x 3 stages -> smem 64000
#define SMEM_L0 (SM_BUF + 4 * 10240)
#define SMEM_L1 (SM_BUF + 3 * 20480)

// ---- device globals (allocation-free scratch) ----
__device__ float    g_h1 [NB * NT * DD];        // layer-0 output, f32 (self term L1)
__device__ float    g_agg[MSPLIT * NB * NT * DD];
__device__ uint32_t g_xhi [NB * NT * DD / 2];   // X fp16x2 [b][row][16]
__device__ uint32_t g_h1h [NB * NT * DD / 2];   // h1 fp16x2 [b][row][16]
__device__ int      g_cnt[80 * NB];             // last-block counters (self-reset)

__device__ __forceinline__ uint32_t smem_u32(const void* p) {
  uint32_t a;
  asm("{ .reg .u64 t; cvta.to.shared.u64 t, %1; cvt.u32.u64 %0, t; }" : "=r"(a) : "l"(p));
  return a;
}
__device__ __forceinline__ void mma16816(float c[4], const uint32_t a[4],
                                         const uint32_t b[2]) {
  asm volatile(
      "mma.sync.aligned.m16n8k16.row.col.f32.f16.f16.f32 "
      "{%0,%1,%2,%3}, {%4,%5,%6,%7}, {%8,%9}, {%0,%1,%2,%3};"
      : "+f"(c[0]), "+f"(c[1]), "+f"(c[2]), "+f"(c[3])
      : "r"(a[0]), "r"(a[1]), "r"(a[2]), "r"(a[3]), "r"(b[0]), "r"(b[1]));
}
__device__ __forceinline__ void ldsm4(uint32_t r[4], uint32_t addr) {
  asm volatile("ldmatrix.sync.aligned.m8n8.x4.shared.b16 {%0,%1,%2,%3}, [%4];"
               : "=r"(r[0]), "=r"(r[1]), "=r"(r[2]), "=r"(r[3]) : "r"(addr));
}
__device__ __forceinline__ void ldsm4t(uint32_t r[4], uint32_t addr) {
  asm volatile("ldmatrix.sync.aligned.m8n8.x4.trans.shared.b16 {%0,%1,%2,%3}, [%4];"
               : "=r"(r[0]), "=r"(r[1]), "=r"(r[2]), "=r"(r[3]) : "r"(addr));
}
__device__ __forceinline__ void cp16(uint32_t dst, const void* src) {
  asm volatile("cp.async.cg.shared.global [%0], [%1], 16;" :: "r"(dst), "l"(src));
}
#define CP_COMMIT() asm volatile("cp.async.commit_group;")
template <int N> __device__ __forceinline__ void cp_wait() {
  asm volatile("cp.async.wait_group %0;" :: "n"(N));
}
__device__ __forceinline__ float tanh_relu(float s) {
  float r = fmaxf(s, 0.0f), v;
  asm("tanh.approx.f32 %0, %1;" : "=f"(v) : "f"(r));
  return v;
}
__device__ __forceinline__ uint32_t pack_h2(float x, float y) {
  __half2 h = __floats2half2_rn(x, y);
  return *reinterpret_cast<uint32_t*>(&h);
}
__device__ __forceinline__ int atomic_add_acqrel(int* p, int v) {
  int old;
  asm volatile("atom.add.acq_rel.gpu.global.s32 %0, [%1], %2;"
               : "=r"(old) : "l"(p), "r"(v) : "memory");
  return old;
}

// ---- prep: bare fp16 convert of X rows (no transpose needed anymore) ----
// grid (80, NB), 256 threads: 32 rows/block, 1 float4 per thread
__global__ void prep_kernel(const float* __restrict__ src) {
  const int t = threadIdx.x, b = blockIdx.y, r0 = blockIdx.x * 32;
  const int row = t >> 3, q = t & 7;
  float4 v = *(const float4*)(src + ((size_t)b * NT + r0 + row) * DD + q * 4);
  *(uint2*)&g_xhi[((size_t)b * NT + r0 + row) * 16 + q * 2] =
      make_uint2(pack_h2(v.x, v.y), pack_h2(v.z, v.w));
}

// ---- fused layer: partial agg + last-block epilogue ----
// LAYER=0: phase2 B from X tile (trans), 4-stage ring, barrier per 2 iters.
// LAYER=1: phase2 B from h1 tile (trans), 3-stage ring, barrier per iter.
template <int LAYER>
__global__ __launch_bounds__(NTHREADS, 3)
void gnn_layer(const float* __restrict__ hin_p,
               const float* __restrict__ Ws, const float* __restrict__ Wn,
               const float* __restrict__ bias, float* __restrict__ hout_p)
{
  constexpr int STAGE_SZ = LAYER ? 20480 : 10240;
  constexpr int NST      = LAYER ? 3 : 4;
  constexpr int OFF_HM   = LAYER ? 10240 : 0;     // phase-2 B tile offset in stage

  extern __shared__ char sm[];
  const uint32_t sb = smem_u32(sm);
  const int t = threadIdx.x, lane = t & 31, wid = t >> 5;
  const int wr = wid >> 2, wc = wid & 3, g = lane >> 2, tig = lane & 3;
  const int bx = blockIdx.x, b = blockIdx.y, mz = blockIdx.z;
  const int n0 = bx * BN;
  const int mtdiag = bx >> 2, doff = (bx & 3) * 32;

  // Xn tile (persistent): 32 rows x 64B fp16
  {
    const int row = t >> 3, q = t & 7;
    const size_t xi = ((size_t)b * NT + n0 + row) * 16 + q * 2;
    *(uint2*)(sm + SM_XNH + row * 80 + q * 8) = *(const uint2*)(g_xhi + xi);
  }

  // stage fill via cp.async (L0: 2x16B/thread, L1: 4x16B/thread)
  auto issue = [&](int i) {
    const int m0 = (mz * NITH + i) * BM;
    const uint32_t base = sb + SM_BUF + (uint32_t)(i % NST) * STAGE_SZ;
    const size_t rbase = ((size_t)b * NT + m0) * 16;
    #pragma unroll
    for (int k = 0; k < 2; ++k) {
      const int c = t + k * 256;
      const int row = c >> 2, q = c & 3;
      cp16(base + row * 80 + q * 16, g_xhi + rbase + row * 16 + q * 4);
      if (LAYER == 1)
        cp16(base + OFF_HM + row * 80 + q * 16, g_h1h + rbase + row * 16 + q * 4);
    }
    CP_COMMIT();
  };

  // ---- ldmatrix lane addresses ----
  const uint32_t a_addr = sb + SM_XNH +
      (uint32_t)(16 * wr + 8 * ((lane >> 3) & 1) + (lane & 7)) * 80u +
      (uint32_t)(lane >> 4) * 16u;
  const uint32_t b1_addr =
      (uint32_t)(32 * wc + 8 * (lane >> 4) + (lane & 7)) * 80u +
      (uint32_t)((lane >> 3) & 1) * 16u;
  // trans: rows = m (lane&15), 16B covers 8 d; lane>>4 selects d half of pair
  const uint32_t b2_addr = OFF_HM +
      (uint32_t)(32 * wc + (lane & 15)) * 80u +
      (uint32_t)(lane >> 4) * 16u;

  float acc2[4][4];
  #pragma unroll
  for (int nc = 0; nc < 4; ++nc)
    #pragma unroll
    for (int e = 0; e < 4; ++e) acc2[nc][e] = 0.0f;

  uint32_t AH[2][4];

  // one m-tile of work
  auto step = [&](int i) {
    const uint32_t buf = sb + SM_BUF + (uint32_t)(i % NST) * STAGE_SZ;
    const int mt = mz * NITH + i;
    const bool diag = (mt == mtdiag);

    uint32_t BH[2][2][4], BH2[2][2][4];
    #pragma unroll
    for (int kt = 0; kt < 2; ++kt)
      #pragma unroll
      for (int p = 0; p < 2; ++p) {
        ldsm4 (BH[kt][p],  buf + b1_addr + p * 1280u + kt * 32u);
        ldsm4t(BH2[kt][p], buf + b2_addr + kt * 1280u + p * 32u);
      }

    // phase 1: S = Xn·Xm^T
    float acc[4][4];
    #pragma unroll
    for (int mc = 0; mc < 4; ++mc)
      #pragma unroll
      for (int e = 0; e < 4; ++e) acc[mc][e] = 0.0f;
    #pragma unroll
    for (int kt = 0; kt < 2; ++kt)
      #pragma unroll
      for (int mc = 0; mc < 4; ++mc)
        mma16816(acc[mc], AH[kt], &BH[kt][mc >> 1][(mc & 1) * 2]);

    // nonlinearity + self-loop -> phase-2 A frags
    uint32_t sA2[8];
    #pragma unroll
    for (int mc = 0; mc < 4; ++mc) {
      float v0 = tanh_relu(acc[mc][0]);
      float v1 = tanh_relu(acc[mc][1]);
      float v2 = tanh_relu(acc[mc][2]);
      float v3 = tanh_relu(acc[mc][3]);
      if (diag) {
        const int nl = 16 * wr + g;
        const int ml = 32 * wc + 8 * mc + 2 * tig;
        if (ml     == nl + doff)     v0 += 0.5f;
        if (ml + 1 == nl + doff)     v1 += 0.5f;
        if (ml     == nl + 8 + doff) v2 += 0.5f;
        if (ml + 1 == nl + 8 + doff) v3 += 0.5f;
      }
      sA2[2 * mc]     = pack_h2(v0, v1);
      sA2[2 * mc + 1] = pack_h2(v2, v3);
    }

    // phase 2: agg += S·H
    #pragma unroll
    for (int kt = 0; kt < 2; ++kt)
      #pragma unroll
      for (int nc = 0; nc < 4; ++nc)
        mma16816(acc2[nc], &sA2[4 * kt], &BH2[kt][nc >> 1][(nc & 1) * 2]);
  };

  if (LAYER == 0) {
    issue(0); issue(1);
    cp_wait<0>();
    __syncthreads();                   // Xn + stages 0,1 visible
    ldsm4(AH[0], a_addr);
    ldsm4(AH[1], a_addr + 32);
    for (int iv = 0; iv < NITH; iv += 2) {
      if (iv + 2 < NITH) { issue(iv + 2); issue(iv + 3); }
      step(iv);
      step(iv + 1);
      if (iv + 2 < NITH) cp_wait<0>();
      __syncthreads();                 // stages (iv+2,iv+3) visible; ring safe
    }
  } else {
    issue(0);
    __syncthreads();                   // Xn visible
    ldsm4(AH[0], a_addr);
    ldsm4(AH[1], a_addr + 32);
    for (int i = 0; i < NITH; ++i) {
      if (i + 1 < NITH) { issue(i + 1); cp_wait<1>(); }
      else              { cp_wait<0>(); }
      __syncthreads();
      step(i);
    }
    __syncthreads();                   // stage region dead -> reduction buffer
  }

  // ---- cross-warp reduction of agg (4 m-slices) ----
  float* aggbuf = (float*)(sm + SM_AGG);
  {
    float* p = aggbuf + wc * 1024;
    const int nl = 16 * wr + g;
    #pragma unroll
    for (int nc = 0; nc < 4; ++nc) {
      const int d0 = 8 * nc + 2 * tig;
      p[nl * 32 + d0]           = acc2[nc][0];
      p[nl * 32 + d0 + 1]       = acc2[nc][1];
      p[(nl + 8) * 32 + d0]     = acc2[nc][2];
      p[(nl + 8) * 32 + d0 + 1] = acc2[nc][3];
    }
  }
  __syncthreads();

  // ---- reduce 4 slices (kept in smem) + write partial agg to global slot ----
  {
    float4* a4 = (float4*)aggbuf;
    float4 s = a4[t], s1 = a4[t + 256], s2 = a4[t + 512], s3 = a4[t + 768];
    float4 r = make_float4(s.x + s1.x + s2.x + s3.x, s.y + s1.y + s2.y + s3.y,
                           s.z + s1.z + s2.z + s3.z, s.w + s1.w + s2.w + s3.w);
    a4[t] = r;                                    // own reduced partial -> smem
    float4* gout = (float4*)(g_agg + (((size_t)(mz * NB + b)) * NT + n0) * DD);
    gout[t] = r;
  }

  // ---- last-block detection (release-acquire atomic) ----
  __shared__ int s_last;
  __syncthreads();
  if (t == 0) {
    int old = atomic_add_acqrel(&g_cnt[bx * NB + b], 1);
    s_last = (old == MSPLIT - 1);
    if (old == MSPLIT - 1) g_cnt[bx * NB + b] = 0;   // self-reset for next launch
  }
  __syncthreads();
  if (!s_last) return;

  // ---- epilogue (last block only): out = elu(h·Ws + (own+peer)·Wn + b) ----
  const float* Hin  = (LAYER == 0) ? hin_p : (const float*)g_h1;
  float*       Hout = (LAYER == 0) ? (float*)g_h1 : hout_p;

  float* sW = (float*)(sm + SM_W);
  for (int i = t; i < 2 * DD * DD + DD; i += NTHREADS) {
    float v;
    if (i < 1024)      v = Ws[i];
    else if (i < 2048) v = Wn[i - 1024];
    else               v = bias[i - 2048];
    sW[i] = v;
  }
  __syncthreads();

  const int r = t >> 3, e0 = (t & 7) * 4;
  const int pz = mz ^ 1;                          // peer slot
  float h[DD], a[DD];
  {
    const float4* hr = (const float4*)(Hin + ((size_t)b * NT + n0 + r) * DD);
    const float4* pp = (const float4*)(g_agg + (((size_t)(pz * NB + b)) * NT + n0 + r) * DD);
    const float4* own = (const float4*)(aggbuf + r * DD);
    #pragma unroll
    for (int q = 0; q < 8; ++q) {
      float4 v = hr[q];
      h[4 * q] = v.x; h[4 * q + 1] = v.y; h[4 * q + 2] = v.z; h[4 * q + 3] = v.w;
      float4 x0 = own[q];                          // own partial from smem
      float4 x1 = __ldcg(pp + q);                  // peer via L2
      a[4 * q]     = x0.x + x1.x; a[4 * q + 1] = x0.y + x1.y;
      a[4 * q + 2] = x0.z + x1.z; a[4 * q + 3] = x0.w + x1.w;
    }
  }
  float out[4];
  #pragma unroll
  for (int e = 0; e < 4; ++e) out[e] = sW[2048 + e0 + e];
  #pragma unroll
  for (int d = 0; d < DD; ++d) {
    const float hd = h[d];
    const float ad = a[d];
    const float* ws = sW + d * DD + e0;
    const float* wn = sW + 1024 + d * DD + e0;
    #pragma unroll
    for (int e = 0; e < 4; ++e) out[e] += hd * ws[e] + ad * wn[e];
  }
  #pragma unroll
  for (int e = 0; e < 4; ++e) {
    float v = out[e];
    out[e] = v > 0.0f ? v : (__expf(v) - 1.0f);
  }
  *(float4*)(Hout + ((size_t)b * NT + n0 + r) * DD + e0) =
      make_float4(out[0], out[1], out[2], out[3]);

  // ---- L0 only: also write h1 in fp16 row-major (no transpose staging) ----
  if (LAYER == 0) {
    *(uint2*)&g_h1h[((size_t)b * NT + n0 + r) * 16 + (t & 7) * 2] =
        make_uint2(pack_h2(out[0], out[1]), pack_h2(out[2], out[3]));
  }
}

extern "C" void kernel_launch(void* const* d_in, const int* in_sizes, int n_in,
                              void* d_out, int out_size) {
  (void)in_sizes; (void)n_in; (void)out_size;
  const float* X  = (const float*)d_in[0];
  const float* Ws = (const float*)d_in[1];   // [2,32,32]
  const float* Wn = (const float*)d_in[2];   // [2,32,32]
  const float* bb = (const float*)d_in[3];   // [2,32]
  float* out = (float*)d_out;

  cudaFuncSetAttribute(gnn_layer<0>,
                       cudaFuncAttributeMaxDynamicSharedMemorySize, SMEM_L0);
  cudaFuncSetAttribute(gnn_layer<1>,
                       cudaFuncAttributeMaxDynamicSharedMemorySize, SMEM_L1);

  dim3 pgrid(80, NB), pblk(256);
  dim3 ggrid(80, NB, MSPLIT), gblk(NTHREADS);

  prep_kernel<<<pgrid, pblk>>>(X);                                   // g_xhi
  gnn_layer<0><<<ggrid, gblk, SMEM_L0>>>(X, Ws, Wn, bb, nullptr);    // g_h1 + g_h1h
  gnn_layer<1><<<ggrid, gblk, SMEM_L1>>>(nullptr, Ws + 1024, Wn + 1024,
                                         bb + 32, out);
}